// round 7
// baseline (speedup 1.0000x reference)
#include <cuda_runtime.h>

// AggregateJoint: per-row block-diagonal MLP 64 -> (16x16) -> (16x3)
// with leaky_relu + folded batchnorm. Shapes fixed: x (256, 64, 512).
//
// Design: one thread per (TWO adjacent f columns) x (8 of the 16 parts).
// Parts partition the 64 x-indices, so splitting parts across threads adds
// no duplicate global traffic while doubling warp parallelism vs R3
// (occ was the limiter: 20.6%). Weights in smem, loaded once per part and
// used for both f columns. Math in packed fp32 (fma.rn.f32x2, sm_103a),
// pairs along hidden dim -> weight pairs are contiguous 16B smem loads.
// BN folded to scale/shift. x loads LDG.64, stores STG.64, coalesced.

#define B_DIM 256
#define N_DIM 64
#define F_DIM 512
#define P_DIM 16
#define IN_DIM 4
#define H_DIM 16
#define O_DIM 3
#define P_PER_THREAD 8

typedef unsigned long long u64;

__device__ __forceinline__ u64 f2fma(u64 a, u64 b, u64 c) {
    u64 d;
    asm("fma.rn.f32x2 %0, %1, %2, %3;" : "=l"(d) : "l"(a), "l"(b), "l"(c));
    return d;
}
__device__ __forceinline__ u64 f2mul(u64 a, u64 b) {
    u64 d;
    asm("mul.rn.f32x2 %0, %1, %2;" : "=l"(d) : "l"(a), "l"(b));
    return d;
}
__device__ __forceinline__ u64 packf2(float lo, float hi) {
    u64 r;
    asm("mov.b64 %0, {%1, %2};" : "=l"(r) : "f"(lo), "f"(hi));
    return r;
}
__device__ __forceinline__ void unpackf2(u64 v, float& lo, float& hi) {
    asm("mov.b64 {%0, %1}, %2;" : "=f"(lo), "=f"(hi) : "l"(v));
}

__global__ __launch_bounds__(256)
void aggregate_joint_kernel(
    const float* __restrict__ x, const int* __restrict__ parts,
    const float* __restrict__ W1, const float* __restrict__ b1,
    const float* __restrict__ W2, const float* __restrict__ b2,
    const float* __restrict__ gamma, const float* __restrict__ beta,
    const float* __restrict__ mean, const float* __restrict__ var,
    float* __restrict__ out)
{
    __shared__ __align__(16) float sW1[P_DIM * IN_DIM * H_DIM];   // [p][i][h], 1024
    __shared__ __align__(16) float sW2T[P_DIM * O_DIM * H_DIM];   // [p][o][h], 768
    __shared__ __align__(16) float sB1[P_DIM * H_DIM];            // 256
    __shared__ float sScale[P_DIM * O_DIM];                        // 48
    __shared__ float sShift[P_DIM * O_DIM];                        // 48
    __shared__ int   sN[N_DIM];                                    // 64

    const int tid = threadIdx.x;

    // ---- stage weights into smem, fold BN ----
    for (int idx = tid; idx < P_DIM * IN_DIM * H_DIM; idx += 256)
        sW1[idx] = W1[idx];
    for (int idx = tid; idx < P_DIM * O_DIM * H_DIM; idx += 256) {
        int p = idx / (O_DIM * H_DIM);
        int rem = idx % (O_DIM * H_DIM);
        int o = rem >> 4;       // rem / 16
        int hh = rem & 15;      // rem % 16
        sW2T[idx] = W2[(p * H_DIM + hh) * O_DIM + o];
    }
    sB1[tid] = b1[tid];
    if (tid < P_DIM * O_DIM) {
        float s = gamma[tid] * rsqrtf(var[tid] + 1e-5f);
        sScale[tid] = s;
        sShift[tid] = (b2[tid] - mean[tid]) * s + beta[tid];
    }
    if (tid < N_DIM) sN[tid] = parts[tid];
    __syncthreads();

    // ---- per-thread: two adjacent f columns, 8 parts ----
    // t bits: [8 low] f-pair (coalesced), [bit 8] part-group, [rest] batch
    const int t = blockIdx.x * 256 + tid;
    const int b = t >> 9;
    const int pg = (t >> 8) & 1;
    const int f = (t & 255) << 1;                  // even f
    const int p0 = pg * P_PER_THREAD;
    const float* xrow = x + (size_t)b * N_DIM * F_DIM + f;
    float* orow = out + (size_t)b * (P_DIM * O_DIM) * F_DIM + f;

    // leaky(x) = 0.505*x + 0.495*|x|
    const u64 AP = packf2(0.505f, 0.505f);
    const u64 BP = packf2(0.495f, 0.495f);

    float2 xc[IN_DIM];
#pragma unroll
    for (int i = 0; i < IN_DIM; i++)
        xc[i] = *(const float2*)&xrow[(size_t)sN[p0 * IN_DIM + i] * F_DIM];

#pragma unroll 1
    for (int pp = 0; pp < P_PER_THREAD; pp++) {
        const int p = p0 + pp;
        // prefetch next part's x (wraps harmlessly within this thread's group)
        float2 xn[IN_DIM];
        const int pn = p0 + ((pp + 1) & (P_PER_THREAD - 1));
#pragma unroll
        for (int i = 0; i < IN_DIM; i++)
            xn[i] = *(const float2*)&xrow[(size_t)sN[pn * IN_DIM + i] * F_DIM];

        // splat each column's x scalar into an f32x2 operand
        u64 xa[IN_DIM], xb[IN_DIM];
#pragma unroll
        for (int i = 0; i < IN_DIM; i++) {
            xa[i] = packf2(xc[i].x, xc[i].x);
            xb[i] = packf2(xc[i].y, xc[i].y);
        }

        // h pairs init from b1 (shared by both columns)
        const ulonglong2* bb = (const ulonglong2*)&sB1[p * H_DIM];
        ulonglong2 t0 = bb[0], t1 = bb[1], t2 = bb[2], t3 = bb[3];
        u64 ha[8] = {t0.x, t0.y, t1.x, t1.y, t2.x, t2.y, t3.x, t3.y};
        u64 hb[8] = {t0.x, t0.y, t1.x, t1.y, t2.x, t2.y, t3.x, t3.y};

        // layer 1: h += x[i] * W1[p][i][:]; weights loaded ONCE, used twice
#pragma unroll
        for (int i = 0; i < IN_DIM; i++) {
            const ulonglong2* wr = (const ulonglong2*)&sW1[(p * IN_DIM + i) * H_DIM];
            ulonglong2 w0 = wr[0], w1 = wr[1], w2r = wr[2], w3 = wr[3];
            ha[0] = f2fma(xa[i], w0.x, ha[0]);  hb[0] = f2fma(xb[i], w0.x, hb[0]);
            ha[1] = f2fma(xa[i], w0.y, ha[1]);  hb[1] = f2fma(xb[i], w0.y, hb[1]);
            ha[2] = f2fma(xa[i], w1.x, ha[2]);  hb[2] = f2fma(xb[i], w1.x, hb[2]);
            ha[3] = f2fma(xa[i], w1.y, ha[3]);  hb[3] = f2fma(xb[i], w1.y, hb[3]);
            ha[4] = f2fma(xa[i], w2r.x, ha[4]); hb[4] = f2fma(xb[i], w2r.x, hb[4]);
            ha[5] = f2fma(xa[i], w2r.y, ha[5]); hb[5] = f2fma(xb[i], w2r.y, hb[5]);
            ha[6] = f2fma(xa[i], w3.x, ha[6]);  hb[6] = f2fma(xb[i], w3.x, hb[6]);
            ha[7] = f2fma(xa[i], w3.y, ha[7]);  hb[7] = f2fma(xb[i], w3.y, hb[7]);
        }

        // packed leaky relu on both columns
#pragma unroll
        for (int j = 0; j < 8; j++) {
            u64 aa = ha[j] & 0x7FFFFFFF7FFFFFFFULL;
            ha[j] = f2fma(aa, BP, f2mul(ha[j], AP));
            u64 ab = hb[j] & 0x7FFFFFFF7FFFFFFFULL;
            hb[j] = f2fma(ab, BP, f2mul(hb[j], AP));
        }

        // layer 2 + BN + leaky + store (weights loaded once per o)
#pragma unroll
        for (int o = 0; o < O_DIM; o++) {
            const ulonglong2* wr = (const ulonglong2*)&sW2T[(p * O_DIM + o) * H_DIM];
            ulonglong2 a0 = wr[0], a1 = wr[1], a2 = wr[2], a3 = wr[3];
            u64 acca = f2mul(ha[0], a0.x);
            u64 accb = f2mul(hb[0], a0.x);
            acca = f2fma(ha[1], a0.y, acca);  accb = f2fma(hb[1], a0.y, accb);
            acca = f2fma(ha[2], a1.x, acca);  accb = f2fma(hb[2], a1.x, accb);
            acca = f2fma(ha[3], a1.y, acca);  accb = f2fma(hb[3], a1.y, accb);
            acca = f2fma(ha[4], a2.x, acca);  accb = f2fma(hb[4], a2.x, accb);
            acca = f2fma(ha[5], a2.y, acca);  accb = f2fma(hb[5], a2.y, accb);
            acca = f2fma(ha[6], a3.x, acca);  accb = f2fma(hb[6], a3.x, accb);
            acca = f2fma(ha[7], a3.y, acca);  accb = f2fma(hb[7], a3.y, accb);

            float la, ha2, lb, hb2;
            unpackf2(acca, la, ha2);
            unpackf2(accb, lb, hb2);
            const float sc = sScale[p * O_DIM + o];
            const float sh = sShift[p * O_DIM + o];
            float va = fmaf(la + ha2, sc, sh);
            float vb = fmaf(lb + hb2, sc, sh);
            va = fmaxf(va, 0.01f * va);
            vb = fmaxf(vb, 0.01f * vb);
            float2 vv = make_float2(va, vb);
            *(float2*)&orow[(size_t)(p * O_DIM + o) * F_DIM] = vv;
        }

#pragma unroll
        for (int i = 0; i < IN_DIM; i++) xc[i] = xn[i];
    }
}

extern "C" void kernel_launch(void* const* d_in, const int* in_sizes, int n_in,
                              void* d_out, int out_size) {
    const float* x     = (const float*)d_in[0];
    const int*   parts = (const int*)d_in[1];
    const float* W1    = (const float*)d_in[2];
    const float* b1    = (const float*)d_in[3];
    const float* W2    = (const float*)d_in[4];
    const float* b2    = (const float*)d_in[5];
    const float* gamma = (const float*)d_in[6];
    const float* beta  = (const float*)d_in[7];
    const float* mean  = (const float*)d_in[8];
    const float* var   = (const float*)d_in[9];
    float* out = (float*)d_out;

    // threads = (B*F/2 f-pairs) * (16/8 part-groups) = 131072
    const int threads_total = (B_DIM * F_DIM / 2) * (P_DIM / P_PER_THREAD);
    const int block = 256;
    const int grid = threads_total / block;   // 512

    aggregate_joint_kernel<<<grid, block>>>(x, parts, W1, b1, W2, b2,
                                            gamma, beta, mean, var, out);
}

// round 8
// speedup vs baseline: 1.0833x; 1.0833x over previous
#include <cuda_runtime.h>

// AggregateJoint: per-row block-diagonal MLP 64 -> (16x16) -> (16x3)
// with leaky_relu + folded batchnorm. Shapes fixed: x (256, 64, 512).
//
// Design (R8): one thread per (FOUR adjacent f columns) x (4 of 16 parts).
// R7 showed occupancy is not the limiter (2x warps, flat time) -> go for
// per-warp ILP + instruction-count instead: weights LDS'd once per part and
// reused across 4 columns (LDS halved), 4 independent FMA chains per h-pair
// (covers FFMA lat), LDG.128 x loads, STG.128 stores. Packed fp32 math
// (fma.rn.f32x2), pairs along hidden dim. BN folded to scale/shift.

#define B_DIM 256
#define N_DIM 64
#define F_DIM 512
#define P_DIM 16
#define IN_DIM 4
#define H_DIM 16
#define O_DIM 3
#define P_PER_THREAD 4
#define COLS 4

typedef unsigned long long u64;

__device__ __forceinline__ u64 f2fma(u64 a, u64 b, u64 c) {
    u64 d;
    asm("fma.rn.f32x2 %0, %1, %2, %3;" : "=l"(d) : "l"(a), "l"(b), "l"(c));
    return d;
}
__device__ __forceinline__ u64 f2mul(u64 a, u64 b) {
    u64 d;
    asm("mul.rn.f32x2 %0, %1, %2;" : "=l"(d) : "l"(a), "l"(b));
    return d;
}
__device__ __forceinline__ u64 packf2(float lo, float hi) {
    u64 r;
    asm("mov.b64 %0, {%1, %2};" : "=l"(r) : "f"(lo), "f"(hi));
    return r;
}
__device__ __forceinline__ void unpackf2(u64 v, float& lo, float& hi) {
    asm("mov.b64 {%0, %1}, %2;" : "=f"(lo), "=f"(hi) : "l"(v));
}

__global__ __launch_bounds__(256, 2)
void aggregate_joint_kernel(
    const float* __restrict__ x, const int* __restrict__ parts,
    const float* __restrict__ W1, const float* __restrict__ b1,
    const float* __restrict__ W2, const float* __restrict__ b2,
    const float* __restrict__ gamma, const float* __restrict__ beta,
    const float* __restrict__ mean, const float* __restrict__ var,
    float* __restrict__ out)
{
    __shared__ __align__(16) float sW1[P_DIM * IN_DIM * H_DIM];   // [p][i][h], 1024
    __shared__ __align__(16) float sW2T[P_DIM * O_DIM * H_DIM];   // [p][o][h], 768
    __shared__ __align__(16) float sB1[P_DIM * H_DIM];            // 256
    __shared__ float sScale[P_DIM * O_DIM];                        // 48
    __shared__ float sShift[P_DIM * O_DIM];                        // 48
    __shared__ int   sN[N_DIM];                                    // 64

    const int tid = threadIdx.x;

    // ---- stage weights into smem, fold BN ----
    for (int idx = tid; idx < P_DIM * IN_DIM * H_DIM; idx += 256)
        sW1[idx] = W1[idx];
    for (int idx = tid; idx < P_DIM * O_DIM * H_DIM; idx += 256) {
        int p = idx / (O_DIM * H_DIM);
        int rem = idx % (O_DIM * H_DIM);
        int o = rem >> 4;       // rem / 16
        int hh = rem & 15;      // rem % 16
        sW2T[idx] = W2[(p * H_DIM + hh) * O_DIM + o];
    }
    sB1[tid] = b1[tid];
    if (tid < P_DIM * O_DIM) {
        float s = gamma[tid] * rsqrtf(var[tid] + 1e-5f);
        sScale[tid] = s;
        sShift[tid] = (b2[tid] - mean[tid]) * s + beta[tid];
    }
    if (tid < N_DIM) sN[tid] = parts[tid];
    __syncthreads();

    // ---- per-thread: four adjacent f columns, 4 parts ----
    // t bits: [7 low] f-quad (coalesced), [7:9) part-group, [rest] batch
    const int t = blockIdx.x * 256 + tid;
    const int b = t >> 9;
    const int pg = (t >> 7) & 3;
    const int f = (t & 127) << 2;                  // f multiple of 4
    const int p0 = pg * P_PER_THREAD;
    const float* xrow = x + (size_t)b * N_DIM * F_DIM + f;
    float* orow = out + (size_t)b * (P_DIM * O_DIM) * F_DIM + f;

    // leaky(x) = 0.505*x + 0.495*|x|
    const u64 AP = packf2(0.505f, 0.505f);
    const u64 BP = packf2(0.495f, 0.495f);

    float4 xc[IN_DIM];
#pragma unroll
    for (int i = 0; i < IN_DIM; i++)
        xc[i] = *(const float4*)&xrow[(size_t)sN[p0 * IN_DIM + i] * F_DIM];

#pragma unroll 1
    for (int pp = 0; pp < P_PER_THREAD; pp++) {
        const int p = p0 + pp;
        // prefetch next part's x (wraps harmlessly within this thread's group)
        float4 xn[IN_DIM];
        const int pn = p0 + ((pp + 1) & (P_PER_THREAD - 1));
#pragma unroll
        for (int i = 0; i < IN_DIM; i++)
            xn[i] = *(const float4*)&xrow[(size_t)sN[pn * IN_DIM + i] * F_DIM];

        // h pairs init from b1 (shared by all 4 columns)
        const ulonglong2* bb = (const ulonglong2*)&sB1[p * H_DIM];
        ulonglong2 t0 = bb[0], t1 = bb[1], t2 = bb[2], t3 = bb[3];
        u64 h[COLS][8];
#pragma unroll
        for (int c = 0; c < COLS; c++) {
            h[c][0] = t0.x; h[c][1] = t0.y; h[c][2] = t1.x; h[c][3] = t1.y;
            h[c][4] = t2.x; h[c][5] = t2.y; h[c][6] = t3.x; h[c][7] = t3.y;
        }

        // layer 1: h[c] += x[c][i] * W1[p][i][:]; weights loaded ONCE per i
#pragma unroll
        for (int i = 0; i < IN_DIM; i++) {
            const ulonglong2* wr = (const ulonglong2*)&sW1[(p * IN_DIM + i) * H_DIM];
            ulonglong2 w0 = wr[0], w1 = wr[1], w2r = wr[2], w3 = wr[3];
            const u64 w[8] = {w0.x, w0.y, w1.x, w1.y, w2r.x, w2r.y, w3.x, w3.y};
            u64 s[COLS];
            s[0] = packf2(xc[i].x, xc[i].x);
            s[1] = packf2(xc[i].y, xc[i].y);
            s[2] = packf2(xc[i].z, xc[i].z);
            s[3] = packf2(xc[i].w, xc[i].w);
#pragma unroll
            for (int j = 0; j < 8; j++) {
#pragma unroll
                for (int c = 0; c < COLS; c++)
                    h[c][j] = f2fma(s[c], w[j], h[c][j]);
            }
        }

        // packed leaky relu on all columns
#pragma unroll
        for (int c = 0; c < COLS; c++) {
#pragma unroll
            for (int j = 0; j < 8; j++) {
                u64 ab = h[c][j] & 0x7FFFFFFF7FFFFFFFULL;
                h[c][j] = f2fma(ab, BP, f2mul(h[c][j], AP));
            }
        }

        // layer 2 + BN + leaky + store (weights loaded once per o)
#pragma unroll
        for (int o = 0; o < O_DIM; o++) {
            const ulonglong2* wr = (const ulonglong2*)&sW2T[(p * O_DIM + o) * H_DIM];
            ulonglong2 a0 = wr[0], a1 = wr[1], a2 = wr[2], a3 = wr[3];
            const u64 a[8] = {a0.x, a0.y, a1.x, a1.y, a2.x, a2.y, a3.x, a3.y};
            u64 acc[COLS];
#pragma unroll
            for (int c = 0; c < COLS; c++)
                acc[c] = f2mul(h[c][0], a[0]);
#pragma unroll
            for (int j = 1; j < 8; j++) {
#pragma unroll
                for (int c = 0; c < COLS; c++)
                    acc[c] = f2fma(h[c][j], a[j], acc[c]);
            }
            const float sc = sScale[p * O_DIM + o];
            const float sh = sShift[p * O_DIM + o];
            float4 vv;
            {
                float lo, hi;
                unpackf2(acc[0], lo, hi);
                float v = fmaf(lo + hi, sc, sh);
                vv.x = fmaxf(v, 0.01f * v);
                unpackf2(acc[1], lo, hi);
                v = fmaf(lo + hi, sc, sh);
                vv.y = fmaxf(v, 0.01f * v);
                unpackf2(acc[2], lo, hi);
                v = fmaf(lo + hi, sc, sh);
                vv.z = fmaxf(v, 0.01f * v);
                unpackf2(acc[3], lo, hi);
                v = fmaf(lo + hi, sc, sh);
                vv.w = fmaxf(v, 0.01f * v);
            }
            *(float4*)&orow[(size_t)(p * O_DIM + o) * F_DIM] = vv;
        }

#pragma unroll
        for (int i = 0; i < IN_DIM; i++) xc[i] = xn[i];
    }
}

extern "C" void kernel_launch(void* const* d_in, const int* in_sizes, int n_in,
                              void* d_out, int out_size) {
    const float* x     = (const float*)d_in[0];
    const int*   parts = (const int*)d_in[1];
    const float* W1    = (const float*)d_in[2];
    const float* b1    = (const float*)d_in[3];
    const float* W2    = (const float*)d_in[4];
    const float* b2    = (const float*)d_in[5];
    const float* gamma = (const float*)d_in[6];
    const float* beta  = (const float*)d_in[7];
    const float* mean  = (const float*)d_in[8];
    const float* var   = (const float*)d_in[9];
    float* out = (float*)d_out;

    // threads = (B*F/4 f-quads) * (16/4 part-groups) = 131072
    const int threads_total = (B_DIM * F_DIM / COLS) * (P_DIM / P_PER_THREAD);
    const int block = 256;
    const int grid = threads_total / block;   // 512

    aggregate_joint_kernel<<<grid, block>>>(x, parts, W1, b1, W2, b2,
                                            gamma, beta, mean, var, out);
}